// round 14
// baseline (speedup 1.0000x reference)
#include <cuda_runtime.h>
#include <cuda_fp16.h>
#include <math.h>
#include <stdint.h>

// ---------------- problem constants ----------------
#define BB      2
#define SS      4096
#define HID     768
#define LAYERS  4
#define HEADS   12
#define HD      64
#define WIN     128          // one-sided window
#define MROWS   (BB*SS)      // 8192 token rows
#define QS      2304         // fused QKV row stride

// ---------------- scratch (device globals; no allocation) ----------------
__device__ __align__(256) float  g_h  [MROWS * HID];
__device__ __align__(256) __half g_hb [MROWS * HID];
__device__ __align__(256) __half g_qkv[MROWS * QS];
__device__ __align__(256) __half g_ab [MROWS * HID];
__device__ __align__(256) __half g_tb [MROWS * HID];
__device__ __align__(256) __half g_fb [MROWS * 4 * HID];
// preprocessed weights: transposed to [N][K], half
__device__ __align__(256) __half g_wqkv[LAYERS * QS * HID];
__device__ __align__(256) float  g_bqkv[LAYERS * QS];
__device__ __align__(256) __half g_wo [LAYERS * HID * HID];
__device__ __align__(256) __half g_wi [LAYERS * 4 * HID * HID];
__device__ __align__(256) __half g_wf [LAYERS * HID * 4 * HID];

// =======================================================================
// helpers
// =======================================================================
__device__ __forceinline__ void mma_f16(
    float& d0, float& d1, float& d2, float& d3,
    uint32_t a0, uint32_t a1, uint32_t a2, uint32_t a3,
    uint32_t b0, uint32_t b1)
{
    asm volatile(
        "mma.sync.aligned.m16n8k16.row.col.f32.f16.f16.f32 "
        "{%0,%1,%2,%3}, {%4,%5,%6,%7}, {%8,%9}, {%0,%1,%2,%3};"
        : "+f"(d0), "+f"(d1), "+f"(d2), "+f"(d3)
        : "r"(a0), "r"(a1), "r"(a2), "r"(a3), "r"(b0), "r"(b1));
}
__device__ __forceinline__ void cp16(uint32_t dst, const void* src) {
    asm volatile("cp.async.cg.shared.global [%0], [%1], 16;"
                 :: "r"(dst), "l"(src));
}
__device__ __forceinline__ void cp16z(uint32_t dst, const void* src, int srcbytes) {
    asm volatile("cp.async.cg.shared.global [%0], [%1], 16, %2;"
                 :: "r"(dst), "l"(src), "r"(srcbytes));
}
__device__ __forceinline__ void ldsm_x4(uint32_t* r, uint32_t addr) {
    asm volatile("ldmatrix.sync.aligned.m8n8.x4.shared.b16 {%0,%1,%2,%3}, [%4];"
        : "=r"(r[0]), "=r"(r[1]), "=r"(r[2]), "=r"(r[3]) : "r"(addr));
}
__device__ __forceinline__ void ldsm_x4_t(uint32_t* r, uint32_t addr) {
    asm volatile("ldmatrix.sync.aligned.m8n8.x4.trans.shared.b16 {%0,%1,%2,%3}, [%4];"
        : "=r"(r[0]), "=r"(r[1]), "=r"(r[2]), "=r"(r[3]) : "r"(addr));
}
__device__ __forceinline__ float warp_sum(float v) {
#pragma unroll
    for (int o = 16; o; o >>= 1) v += __shfl_xor_sync(0xffffffffu, v, o);
    return v;
}

// =======================================================================
// fp16 mma.sync GEMM, cp.async 4-stage pipeline, ldmatrix fragment loads.
// act=0: fp32 C.  act=1: GELU, half C.  act=2: plain, half C.
// =======================================================================
#define TILE_BYTES (128*64)
#define STG_BYTES  (2*TILE_BYTES)
#define NSTAGE     4
#define GEMM_SMEM_BYTES (NSTAGE*STG_BYTES)    // 64 KB

__global__ __launch_bounds__(256, 2) void gemm_f16_kernel(
    const __half* __restrict__ A, const __half* __restrict__ Bw,
    const float* __restrict__ bias, void* __restrict__ Cout,
    int M, int N, int K, int act)
{
    extern __shared__ uint32_t smu[];
    uint32_t smem_base = (uint32_t)__cvta_generic_to_shared(smu);

    const int tid  = threadIdx.x;
    const int lane = tid & 31;
    const int wid  = tid >> 5;
    const int lm   = lane >> 2;
    const int lk   = lane & 3;
    const int jr   = lane & 7;
    const int jg   = lane >> 3;
    const int warp_m = (wid >> 1) * 32;
    const int warp_n = (wid & 1) * 64;
    const int bm = blockIdx.y * 128;
    const int bn = blockIdx.x * 128;

    const __half* Ag = A  + (size_t)bm * K;
    const __half* Bg = Bw + (size_t)bn * K;

    const int r0 = tid >> 2, q0c = tid & 3;
    const int r1 = r0 + 64;
    const uint32_t offA0 = (uint32_t)(r0 * 64 + (q0c ^ ((r0 >> 1) & 3)) * 16);
    const uint32_t offA1 = (uint32_t)(r1 * 64 + (q0c ^ ((r1 >> 1) & 3)) * 16);

    uint32_t offAf[2][2], offBf[4][2];
#pragma unroll
    for (int mt = 0; mt < 2; ++mt) {
        int row = warp_m + mt * 16 + ((jg & 1) << 3) + jr;
        int sw = (row >> 1) & 3;
#pragma unroll
        for (int s = 0; s < 2; ++s) {
            int quad = 2 * s + (jg >> 1);
            offAf[mt][s] = (uint32_t)(row * 64 + ((quad ^ sw) * 16));
        }
    }
#pragma unroll
    for (int ng = 0; ng < 4; ++ng) {
        int row = warp_n + (2 * ng + (jg >> 1)) * 8 + jr;
        int sw = (row >> 1) & 3;
#pragma unroll
        for (int s = 0; s < 2; ++s) {
            int quad = 2 * s + (jg & 1);
            offBf[ng][s] = (uint32_t)(TILE_BYTES + row * 64 + ((quad ^ sw) * 16));
        }
    }

    float acc[2][8][4];
#pragma unroll
    for (int mt = 0; mt < 2; ++mt)
#pragma unroll
        for (int nt = 0; nt < 8; ++nt)
#pragma unroll
            for (int c = 0; c < 4; ++c) acc[mt][nt][c] = 0.f;

    const int NC = K >> 5;

    auto issue = [&](int c, int stg) {
        uint32_t sA = smem_base + (uint32_t)stg * STG_BYTES;
        uint32_t sB = sA + TILE_BYTES;
        const __half* ag = Ag + c * 32;
        const __half* bg = Bg + c * 32;
        cp16(sA + offA0, ag + (size_t)r0 * K + q0c * 8);
        cp16(sA + offA1, ag + (size_t)r1 * K + q0c * 8);
        cp16(sB + offA0, bg + (size_t)r0 * K + q0c * 8);
        cp16(sB + offA1, bg + (size_t)r1 * K + q0c * 8);
    };

#pragma unroll
    for (int p = 0; p < 3; ++p) {
        if (p < NC) issue(p, p);
        asm volatile("cp.async.commit_group;" ::: "memory");
    }

    for (int c = 0; c < NC; ++c) {
        asm volatile("cp.async.wait_group 2;" ::: "memory");
        __syncthreads();
        if (c + 3 < NC) issue(c + 3, (c + 3) % NSTAGE);
        asm volatile("cp.async.commit_group;" ::: "memory");

        const uint32_t stage = smem_base + (uint32_t)(c % NSTAGE) * STG_BYTES;
#pragma unroll
        for (int s = 0; s < 2; ++s) {
            uint32_t a[2][4];
            ldsm_x4(a[0], stage + offAf[0][s]);
            ldsm_x4(a[1], stage + offAf[1][s]);
            uint32_t bf[4][4];
#pragma unroll
            for (int ng = 0; ng < 4; ++ng)
                ldsm_x4(bf[ng], stage + offBf[ng][s]);
#pragma unroll
            for (int mt = 0; mt < 2; ++mt)
#pragma unroll
                for (int nt = 0; nt < 8; ++nt)
                    mma_f16(acc[mt][nt][0], acc[mt][nt][1],
                            acc[mt][nt][2], acc[mt][nt][3],
                            a[mt][0], a[mt][1], a[mt][2], a[mt][3],
                            bf[nt >> 1][(nt & 1) * 2],
                            bf[nt >> 1][(nt & 1) * 2 + 1]);
        }
    }

    // ---- epilogue ----
#pragma unroll
    for (int mt = 0; mt < 2; ++mt) {
        int row0 = bm + warp_m + mt * 16 + lm;
#pragma unroll
        for (int nt = 0; nt < 8; ++nt) {
            int col = bn + warp_n + nt * 8 + 2 * lk;
            float b0 = bias[col], b1 = bias[col + 1];
            float v0 = acc[mt][nt][0] + b0;
            float v1 = acc[mt][nt][1] + b1;
            float v2 = acc[mt][nt][2] + b0;
            float v3 = acc[mt][nt][3] + b1;
            if (act == 0) {
                float* C = (float*)Cout;
                *(float2*)(C + (size_t)row0 * N + col) = make_float2(v0, v1);
                *(float2*)(C + (size_t)(row0 + 8) * N + col) = make_float2(v2, v3);
            } else {
                if (act == 1) {
                    v0 = 0.5f * v0 * (1.0f + erff(v0 * 0.7071067811865476f));
                    v1 = 0.5f * v1 * (1.0f + erff(v1 * 0.7071067811865476f));
                    v2 = 0.5f * v2 * (1.0f + erff(v2 * 0.7071067811865476f));
                    v3 = 0.5f * v3 * (1.0f + erff(v3 * 0.7071067811865476f));
                }
                __half* C = (__half*)Cout;
                *(__half2*)(C + (size_t)row0 * N + col) = __floats2half2_rn(v0, v1);
                *(__half2*)(C + (size_t)(row0 + 8) * N + col) = __floats2half2_rn(v2, v3);
            }
        }
    }
}

// =======================================================================
// weight preprocessing: transpose fp32 [K,N] -> half [N,K], batched layers
// =======================================================================
__global__ __launch_bounds__(256) void transpose_h_kernel(
    const float* __restrict__ src, __half* __restrict__ dst, int K, int N,
    size_t sstride, size_t dstride)
{
    __shared__ float t[32][33];
    src += (size_t)blockIdx.z * sstride;
    dst += (size_t)blockIdx.z * dstride;
    int tx = threadIdx.x, ty = threadIdx.y;
    int x = blockIdx.x * 32 + tx;
    int y0 = blockIdx.y * 32;
#pragma unroll
    for (int j = 0; j < 32; j += 8)
        t[ty + j][tx] = src[(size_t)(y0 + ty + j) * N + x];
    __syncthreads();
    int n_out = blockIdx.x * 32 + ty;
#pragma unroll
    for (int j = 0; j < 32; j += 8)
        dst[(size_t)(n_out + j) * K + y0 + tx] = __float2half_rn(t[tx][ty + j]);
}

__global__ __launch_bounds__(256) void bias_qkv_kernel(
    const float* __restrict__ bq, const float* __restrict__ bk,
    const float* __restrict__ bv, float* __restrict__ bout)
{
    int idx = blockIdx.x * 256 + threadIdx.x;
    if (idx >= LAYERS * QS) return;
    int l = idx / QS, j = idx % QS;
    const float* src = (j < HID) ? bq : (j < 2 * HID) ? bk : bv;
    bout[idx] = src[(size_t)l * HID + (j % HID)];
}

// =======================================================================
// embeddings + LN : warp-per-row, 8 rows per 256-thread block.
// lane holds 24 elements as 6 x float4 (col4 = lane*4 + 128*i).
// =======================================================================
__global__ __launch_bounds__(256) void embed_ln_kernel(
    const float* __restrict__ emb, const float* __restrict__ pos,
    const float* __restrict__ tok, const float* __restrict__ g,
    const float* __restrict__ b, float* __restrict__ out,
    __half* __restrict__ out_h)
{
    const int w = threadIdx.x >> 5, lane = threadIdx.x & 31;
    const int row = blockIdx.x * 8 + w;
    const int s = row & (SS - 1);
    const size_t rb = (size_t)row * HID;
    const size_t pb = (size_t)(s + 1) * HID;

    float4 x[6];
    float ls = 0.f;
#pragma unroll
    for (int i = 0; i < 6; ++i) {
        int j = lane * 4 + i * 128;
        float4 e = *(const float4*)(emb + rb + j);
        float4 p = *(const float4*)(pos + pb + j);
        float4 t = *(const float4*)(tok + j);
        x[i].x = e.x + p.x + t.x; x[i].y = e.y + p.y + t.y;
        x[i].z = e.z + p.z + t.z; x[i].w = e.w + p.w + t.w;
        ls += x[i].x + x[i].y + x[i].z + x[i].w;
    }
    float mean = warp_sum(ls) * (1.f / HID);
    float d2 = 0.f;
#pragma unroll
    for (int i = 0; i < 6; ++i) {
        float a0 = x[i].x - mean, a1 = x[i].y - mean;
        float a2 = x[i].z - mean, a3 = x[i].w - mean;
        d2 += a0 * a0 + a1 * a1 + a2 * a2 + a3 * a3;
    }
    float rs = rsqrtf(warp_sum(d2) * (1.f / HID) + 1e-12f);
#pragma unroll
    for (int i = 0; i < 6; ++i) {
        int j = lane * 4 + i * 128;
        float4 gg = *(const float4*)(g + j);
        float4 bb = *(const float4*)(b + j);
        float4 v;
        v.x = (x[i].x - mean) * rs * gg.x + bb.x;
        v.y = (x[i].y - mean) * rs * gg.y + bb.y;
        v.z = (x[i].z - mean) * rs * gg.z + bb.z;
        v.w = (x[i].w - mean) * rs * gg.w + bb.w;
        *(float4*)(out + rb + j) = v;
        __half2 h0 = __floats2half2_rn(v.x, v.y);
        __half2 h1 = __floats2half2_rn(v.z, v.w);
        uint2 hh = make_uint2(*(uint32_t*)&h0, *(uint32_t*)&h1);
        *(uint2*)(out_h + rb + j) = hh;
    }
}

// =======================================================================
// residual add + LN, warp-per-row. Optional fused final projection:
// if fout != nullptr, also computes sigmoid(dot(v, Wp) + bp) -> fout[row].
// =======================================================================
__global__ __launch_bounds__(256) void add_ln_kernel(
    const float* __restrict__ hin, const __half* __restrict__ xin,
    const float* __restrict__ g, const float* __restrict__ b,
    float* __restrict__ out, __half* __restrict__ out_h,
    const float* __restrict__ Wp, const float* __restrict__ bp,
    float* __restrict__ fout)
{
    const int w = threadIdx.x >> 5, lane = threadIdx.x & 31;
    const int row = blockIdx.x * 8 + w;
    const size_t rb = (size_t)row * HID;

    float4 x[6];
    float ls = 0.f;
#pragma unroll
    for (int i = 0; i < 6; ++i) {
        int j = lane * 4 + i * 128;
        float4 hv = *(const float4*)(hin + rb + j);
        uint2 xr = *(const uint2*)(xin + rb + j);
        __half2 x0 = *(__half2*)&xr.x, x1 = *(__half2*)&xr.y;
        float2 f0 = __half22float2(x0), f1 = __half22float2(x1);
        x[i].x = hv.x + f0.x; x[i].y = hv.y + f0.y;
        x[i].z = hv.z + f1.x; x[i].w = hv.w + f1.y;
        ls += x[i].x + x[i].y + x[i].z + x[i].w;
    }
    float mean = warp_sum(ls) * (1.f / HID);
    float d2 = 0.f;
#pragma unroll
    for (int i = 0; i < 6; ++i) {
        float a0 = x[i].x - mean, a1 = x[i].y - mean;
        float a2 = x[i].z - mean, a3 = x[i].w - mean;
        d2 += a0 * a0 + a1 * a1 + a2 * a2 + a3 * a3;
    }
    float rs = rsqrtf(warp_sum(d2) * (1.f / HID) + 1e-12f);

    float dot = 0.f;
#pragma unroll
    for (int i = 0; i < 6; ++i) {
        int j = lane * 4 + i * 128;
        float4 gg = *(const float4*)(g + j);
        float4 bb = *(const float4*)(b + j);
        float4 v;
        v.x = (x[i].x - mean) * rs * gg.x + bb.x;
        v.y = (x[i].y - mean) * rs * gg.y + bb.y;
        v.z = (x[i].z - mean) * rs * gg.z + bb.z;
        v.w = (x[i].w - mean) * rs * gg.w + bb.w;
        *(float4*)(out + rb + j) = v;
        __half2 h0 = __floats2half2_rn(v.x, v.y);
        __half2 h1 = __floats2half2_rn(v.z, v.w);
        uint2 hh = make_uint2(*(uint32_t*)&h0, *(uint32_t*)&h1);
        *(uint2*)(out_h + rb + j) = hh;
        if (fout) {
            float4 wp = *(const float4*)(Wp + j);
            dot += v.x * wp.x + v.y * wp.y + v.z * wp.z + v.w * wp.w;
        }
    }
    if (fout) {
        dot = warp_sum(dot);
        if (lane == 0)
            fout[row] = 1.f / (1.f + expf(-(dot + bp[0])));
    }
}

// =======================================================================
// tensor-core banded flash attention, cp.async double-buffered K/V.
// =======================================================================
#define KV_PITCH 72
__global__ __launch_bounds__(128) void attn_tc_kernel(
    const __half* __restrict__ QKV, const int* __restrict__ am,
    __half* __restrict__ Aout)
{
    __shared__ __half Qs[64 * KV_PITCH];
    __shared__ __half Ks[2][64 * KV_PITCH];
    __shared__ __half Vs[2][64 * KV_PITCH];
    __shared__ int kvalAll[320];

    const int tid  = threadIdx.x;
    const int lane = tid & 31;
    const int w    = tid >> 5;
    const int lm   = lane >> 2;
    const int lk   = lane & 3;
    const int jr   = lane & 7;
    const int jg   = lane >> 3;
    const int q0 = blockIdx.x * 64, h = blockIdx.y, b = blockIdx.z;
    const size_t base  = ((size_t)b * SS) * QS + (size_t)h * HD;
    const size_t baseO = ((size_t)b * SS) * HID + (size_t)h * HD;

    const uint32_t qsm  = (uint32_t)__cvta_generic_to_shared(Qs);
    const uint32_t ksm0 = (uint32_t)__cvta_generic_to_shared(Ks[0]);
    const uint32_t vsm0 = (uint32_t)__cvta_generic_to_shared(Vs[0]);
    const uint32_t kbufB = (uint32_t)(64 * KV_PITCH * 2);

    const int rr = tid >> 3, cc8 = (tid & 7) * 8;

    auto issue_kv = [&](int kt, int buf) {
        const int ks = q0 - 128 + kt * 64;
        uint32_t kd = ksm0 + (uint32_t)buf * kbufB;
        uint32_t vd = vsm0 + (uint32_t)buf * kbufB;
#pragma unroll
        for (int it = 0; it < 4; ++it) {
            int r = rr + it * 16;
            int kj = ks + r;
            int ok = ((unsigned)kj < (unsigned)SS) ? 16 : 0;
            int kjc = (kj < 0) ? 0 : ((kj >= SS) ? SS - 1 : kj);
            const __half* src = QKV + base + (size_t)kjc * QS + cc8;
            uint32_t off = (uint32_t)(r * KV_PITCH + cc8) * 2;
            cp16z(kd + off, src + HID, ok);
            cp16z(vd + off, src + 2 * HID, ok);
        }
    };

#pragma unroll
    for (int it = 0; it < 4; ++it) {
        int idx = tid + it * 128;
        int r = idx >> 3, c8 = (idx & 7) * 8;
        *(float4*)&Qs[r * KV_PITCH + c8] =
            *(const float4*)(QKV + base + (size_t)(q0 + r) * QS + c8);
    }
    issue_kv(0, 0);
    asm volatile("cp.async.commit_group;" ::: "memory");
#pragma unroll
    for (int i = 0; i < 3; ++i) {
        int idx = tid + i * 128;
        if (idx < 320) {
            int kj = q0 - 128 + idx;
            kvalAll[idx] = ((unsigned)kj < (unsigned)SS) && (am[(size_t)b * SS + kj] != 0);
        }
    }
    __syncthreads();

    uint32_t qf[4][4];
    {
        int row = w * 16 + ((jg & 1) << 3) + jr;
        int coff = (jg >> 1) << 3;
#pragma unroll
        for (int s = 0; s < 4; ++s)
            ldsm_x4(qf[s], qsm + (uint32_t)(row * KV_PITCH + 16 * s + coff) * 2);
    }

    const int qi0 = q0 + w * 16 + lm;
    const int qi1 = qi0 + 8;

    float m0 = -INFINITY, m1 = -INFINITY, l0 = 0.f, l1 = 0.f;
    float O[8][4];
#pragma unroll
    for (int t = 0; t < 8; ++t)
#pragma unroll
        for (int c = 0; c < 4; ++c) O[t][c] = 0.f;

    for (int kt = 0; kt < 5; ++kt) {
        const int buf = kt & 1;
        const int ks = q0 - 128 + kt * 64;
        asm volatile("cp.async.wait_group 0;" ::: "memory");
        __syncthreads();
        if (kt + 1 < 5) issue_kv(kt + 1, buf ^ 1);
        asm volatile("cp.async.commit_group;" ::: "memory");

        const uint32_t ksm = ksm0 + (uint32_t)buf * kbufB;
        const uint32_t vsm = vsm0 + (uint32_t)buf * kbufB;

        float sacc[8][4];
#pragma unroll
        for (int t = 0; t < 8; ++t) {
#pragma unroll
            for (int c = 0; c < 4; ++c) sacc[t][c] = 0.f;
            uint32_t kf[8];
            int krow = 8 * t + jr;
            ldsm_x4(kf,     ksm + (uint32_t)(krow * KV_PITCH + 8 * jg) * 2);
            ldsm_x4(kf + 4, ksm + (uint32_t)(krow * KV_PITCH + 32 + 8 * jg) * 2);
#pragma unroll
            for (int s = 0; s < 4; ++s)
                mma_f16(sacc[t][0], sacc[t][1], sacc[t][2], sacc[t][3],
                        qf[s][0], qf[s][1], qf[s][2], qf[s][3],
                        kf[2 * s], kf[2 * s + 1]);
        }

        const int moff = kt * 64;
        float rm0 = -INFINITY, rm1 = -INFINITY;
#pragma unroll
        for (int t = 0; t < 8; ++t) {
            int kc = 8 * t + 2 * lk;
            int kj0 = ks + kc, kj1 = kj0 + 1;
            bool v0 = kvalAll[moff + kc] != 0, v1 = kvalAll[moff + kc + 1] != 0;
            float s00 = (v0 && abs(kj0 - qi0) <= WIN) ? sacc[t][0] * 0.125f : -1e9f;
            float s01 = (v1 && abs(kj1 - qi0) <= WIN) ? sacc[t][1] * 0.125f : -1e9f;
            float s10 = (v0 && abs(kj0 - qi1) <= WIN) ? sacc[t][2] * 0.125f : -1e9f;
            float s11 = (v1 && abs(kj1 - qi1) <= WIN) ? sacc[t][3] * 0.125f : -1e9f;
            sacc[t][0] = s00; sacc[t][1] = s01; sacc[t][2] = s10; sacc[t][3] = s11;
            rm0 = fmaxf(rm0, fmaxf(s00, s01));
            rm1 = fmaxf(rm1, fmaxf(s10, s11));
        }
        rm0 = fmaxf(rm0, __shfl_xor_sync(0xffffffffu, rm0, 1));
        rm0 = fmaxf(rm0, __shfl_xor_sync(0xffffffffu, rm0, 2));
        rm1 = fmaxf(rm1, __shfl_xor_sync(0xffffffffu, rm1, 1));
        rm1 = fmaxf(rm1, __shfl_xor_sync(0xffffffffu, rm1, 2));

        float mn0 = fmaxf(m0, rm0), mn1 = fmaxf(m1, rm1);
        float sc0 = __expf(m0 - mn0), sc1 = __expf(m1 - mn1);
        m0 = mn0; m1 = mn1;

        float rs0 = 0.f, rs1 = 0.f;
        uint32_t pf[8][2];
#pragma unroll
        for (int t = 0; t < 8; ++t) {
            float p00 = __expf(sacc[t][0] - mn0);
            float p01 = __expf(sacc[t][1] - mn0);
            float p10 = __expf(sacc[t][2] - mn1);
            float p11 = __expf(sacc[t][3] - mn1);
            rs0 += p00 + p01; rs1 += p10 + p11;
            __half2 h0 = __floats2half2_rn(p00, p01);
            __half2 h1 = __floats2half2_rn(p10, p11);
            pf[t][0] = *(uint32_t*)&h0;
            pf[t][1] = *(uint32_t*)&h1;
        }
        rs0 += __shfl_xor_sync(0xffffffffu, rs0, 1);
        rs0 += __shfl_xor_sync(0xffffffffu, rs0, 2);
        rs1 += __shfl_xor_sync(0xffffffffu, rs1, 1);
        rs1 += __shfl_xor_sync(0xffffffffu, rs1, 2);
        l0 = l0 * sc0 + rs0;
        l1 = l1 * sc1 + rs1;
#pragma unroll
        for (int t = 0; t < 8; ++t) {
            O[t][0] *= sc0; O[t][1] *= sc0;
            O[t][2] *= sc1; O[t][3] *= sc1;
        }

#pragma unroll
        for (int s = 0; s < 4; ++s) {
            uint32_t a0 = pf[2 * s][0], a1 = pf[2 * s][1];
            uint32_t a2 = pf[2 * s + 1][0], a3 = pf[2 * s + 1][1];
            int vrow = 16 * s + ((jg & 1) << 3) + jr;
            int vcb  = (jg >> 1) << 3;
#pragma unroll
            for (int i = 0; i < 4; ++i) {
                uint32_t vf[4];
                ldsm_x4_t(vf, vsm + (uint32_t)(vrow * KV_PITCH + 16 * i + vcb) * 2);
                mma_f16(O[2 * i][0], O[2 * i][1], O[2 * i][2], O[2 * i][3],
                        a0, a1, a2, a3, vf[0], vf[1]);
                mma_f16(O[2 * i + 1][0], O[2 * i + 1][1], O[2 * i + 1][2], O[2 * i + 1][3],
                        a0, a1, a2, a3, vf[2], vf[3]);
            }
        }
    }

    float rl0 = (l0 > 0.f) ? (1.f / l0) : 0.f;
    float rl1 = (l1 > 0.f) ? (1.f / l1) : 0.f;
#pragma unroll
    for (int t = 0; t < 8; ++t) {
        int col = 8 * t + 2 * lk;
        *(__half2*)(Aout + baseO + (size_t)qi0 * HID + col)
            = __floats2half2_rn(O[t][0] * rl0, O[t][1] * rl0);
        *(__half2*)(Aout + baseO + (size_t)qi1 * HID + col)
            = __floats2half2_rn(O[t][2] * rl1, O[t][3] * rl1);
    }
}

// ---------------- host orchestration ----------------
extern "C" void kernel_launch(void* const* d_in, const int* in_sizes, int n_in,
                              void* d_out, int out_size)
{
    const float* emb     = (const float*)d_in[0];
    const int*   amask   = (const int*)  d_in[1];
    const float* pos     = (const float*)d_in[2];
    const float* tok     = (const float*)d_in[3];
    const float* eln_g   = (const float*)d_in[4];
    const float* eln_b   = (const float*)d_in[5];
    const float* Wq      = (const float*)d_in[6];
    const float* bq      = (const float*)d_in[7];
    const float* Wk      = (const float*)d_in[8];
    const float* bk      = (const float*)d_in[9];
    const float* Wv      = (const float*)d_in[10];
    const float* bv      = (const float*)d_in[11];
    const float* Wo      = (const float*)d_in[12];
    const float* bo      = (const float*)d_in[13];
    const float* ln1_g   = (const float*)d_in[14];
    const float* ln1_b   = (const float*)d_in[15];
    const float* Wi      = (const float*)d_in[16];
    const float* bi      = (const float*)d_in[17];
    const float* Wf      = (const float*)d_in[18];
    const float* bf      = (const float*)d_in[19];
    const float* ln2_g   = (const float*)d_in[20];
    const float* ln2_b   = (const float*)d_in[21];
    const float* Wp      = (const float*)d_in[22];
    const float* bp      = (const float*)d_in[23];

    float  *h_, *bqkv_;
    __half *hb_, *qkv_, *ab_, *tb_, *fb_, *wqkv_, *wo_, *wi_, *wf_;
    cudaGetSymbolAddress((void**)&h_,   g_h);
    cudaGetSymbolAddress((void**)&hb_,  g_hb);
    cudaGetSymbolAddress((void**)&qkv_, g_qkv);
    cudaGetSymbolAddress((void**)&ab_,  g_ab);
    cudaGetSymbolAddress((void**)&tb_,  g_tb);
    cudaGetSymbolAddress((void**)&fb_,  g_fb);
    cudaGetSymbolAddress((void**)&wqkv_, g_wqkv);
    cudaGetSymbolAddress((void**)&bqkv_, g_bqkv);
    cudaGetSymbolAddress((void**)&wo_,  g_wo);
    cudaGetSymbolAddress((void**)&wi_,  g_wi);
    cudaGetSymbolAddress((void**)&wf_,  g_wf);

    cudaFuncSetAttribute(gemm_f16_kernel,
                         cudaFuncAttributeMaxDynamicSharedMemorySize, GEMM_SMEM_BYTES);

    const size_t WSQ   = (size_t)HID * HID;
    const size_t WSI   = (size_t)HID * 4 * HID;
    const size_t WSQKV = (size_t)QS * HID;

    // ---- weight preprocessing: batched transposes ----
    {
        dim3 blk(32, 8);
        dim3 gsq(HID / 32, HID / 32, LAYERS);
        transpose_h_kernel<<<gsq, blk>>>(Wq, wqkv_, HID, HID, WSQ, WSQKV);
        transpose_h_kernel<<<gsq, blk>>>(Wk, wqkv_ + (size_t)HID * HID, HID, HID, WSQ, WSQKV);
        transpose_h_kernel<<<gsq, blk>>>(Wv, wqkv_ + (size_t)2 * HID * HID, HID, HID, WSQ, WSQKV);
        transpose_h_kernel<<<gsq, blk>>>(Wo, wo_, HID, HID, WSQ, WSQ);
        dim3 gi(4 * HID / 32, HID / 32, LAYERS);
        transpose_h_kernel<<<gi, blk>>>(Wi, wi_, HID, 4 * HID, WSI, WSI);
        dim3 gf(HID / 32, 4 * HID / 32, LAYERS);
        transpose_h_kernel<<<gf, blk>>>(Wf, wf_, 4 * HID, HID, WSI, WSI);
        bias_qkv_kernel<<<(LAYERS * QS + 255) / 256, 256>>>(bq, bk, bv, bqkv_);
    }

    embed_ln_kernel<<<MROWS / 8, 256>>>(emb, pos, tok, eln_g, eln_b, h_, hb_);

    for (int l = 0; l < LAYERS; ++l) {
        dim3 gqkv(QS / 128, MROWS / 128);
        gemm_f16_kernel<<<gqkv, 256, GEMM_SMEM_BYTES>>>(
            hb_, wqkv_ + l * WSQKV, bqkv_ + (size_t)l * QS, qkv_,
            MROWS, QS, HID, 2);

        dim3 ga(SS / 64, HEADS, BB);
        attn_tc_kernel<<<ga, 128>>>(qkv_, amask, ab_);

        dim3 g1(HID / 128, MROWS / 128);
        gemm_f16_kernel<<<g1, 256, GEMM_SMEM_BYTES>>>(
            ab_, wo_ + l * WSQ, bo + (size_t)l * HID, tb_, MROWS, HID, HID, 2);
        add_ln_kernel<<<MROWS / 8, 256>>>(h_, tb_, ln1_g + l * HID, ln1_b + l * HID,
                                          h_, hb_, nullptr, nullptr, nullptr);

        dim3 g2(4 * HID / 128, MROWS / 128);
        gemm_f16_kernel<<<g2, 256, GEMM_SMEM_BYTES>>>(
            hb_, wi_ + l * WSI, bi + (size_t)l * 4 * HID, fb_,
            MROWS, 4 * HID, HID, 1);
        gemm_f16_kernel<<<g1, 256, GEMM_SMEM_BYTES>>>(
            fb_, wf_ + l * WSI, bf + (size_t)l * HID, tb_, MROWS, HID, 4 * HID, 2);
        // last layer: fuse final projection + sigmoid into the LN
        add_ln_kernel<<<MROWS / 8, 256>>>(h_, tb_, ln2_g + l * HID, ln2_b + l * HID,
                                          h_, hb_,
                                          (l == LAYERS - 1) ? Wp : nullptr,
                                          (l == LAYERS - 1) ? bp : nullptr,
                                          (l == LAYERS - 1) ? (float*)d_out : nullptr);
    }
}